// round 15
// baseline (speedup 1.0000x reference)
#include <cuda_runtime.h>
#include <math.h>
#include <stdint.h>

#define BIGF 1e10f
#define NMAX 3072
#define KMAXG 64
#define TI 16
#define TJ 128
#define TJP 129
#define DTHREADS 64

// Scratch (no allocations allowed).
__device__ float g_dist[(size_t)NMAX * NMAX];
__device__ int g_dst[NMAX * KMAXG];
__device__ int g_src[NMAX * KMAXG];
__device__ unsigned char g_val[NMAX * KMAXG];

// ---------------------------------------------------------------------------
// Packed f32x2 helpers
// ---------------------------------------------------------------------------
static __device__ __forceinline__ unsigned long long pk2(float a, float b) {
  unsigned long long r;
  asm("mov.b64 %0, {%1,%2};" : "=l"(r) : "f"(a), "f"(b));
  return r;
}
static __device__ __forceinline__ void upk2(unsigned long long v, float& a, float& b) {
  asm("mov.b64 {%0,%1}, %2;" : "=f"(a), "=f"(b) : "l"(v));
}
static __device__ __forceinline__ unsigned long long fma2_(unsigned long long a,
                                                           unsigned long long b,
                                                           unsigned long long c) {
  unsigned long long r;
  asm("fma.rn.f32x2 %0, %1, %2, %3;" : "=l"(r) : "l"(a), "l"(b), "l"(c));
  return r;
}
static __device__ __forceinline__ unsigned long long mul2_(unsigned long long a,
                                                           unsigned long long b) {
  unsigned long long r;
  asm("mul.rn.f32x2 %0, %1, %2;" : "=l"(r) : "l"(a), "l"(b));
  return r;
}
static __device__ __forceinline__ unsigned long long add2_(unsigned long long a,
                                                           unsigned long long b) {
  unsigned long long r;
  asm("add.rn.f32x2 %0, %1, %2;" : "=l"(r) : "l"(a), "l"(b));
  return r;
}

// ---------------------------------------------------------------------------
// dist kernel — per-pair math VERBATIM from the passing R13/R14 kernel
// (bit-identical g_dist values); TJ=128 tiles with 64 threads (2 packed
// j/thread) for 2x active-block parallelism and sharper group skips.
// ---------------------------------------------------------------------------
__global__ __launch_bounds__(DTHREADS) void dist_kernel(
    const float* __restrict__ X, const int* __restrict__ Seg,
    const int* __restrict__ bid, int N) {
  __shared__ unsigned long long sNX[TI][4][3];
  __shared__ unsigned long long sSicp[TI][4];
  __shared__ int sB[TI], sS[TI];
  __shared__ int sBj[TJ];
  __shared__ float sD[TI][TJP];

  int i0 = blockIdx.y * TI;
  int j0 = blockIdx.x * TJ;
  if (j0 + TJ - 1 < i0) return;  // tile fully below diagonal
  {
    int iend = min(i0 + TI - 1, N - 1);
    int jend = min(j0 + TJ - 1, N - 1);
    int ia = bid[min(i0, N - 1)], ib = bid[iend];
    int ja = bid[min(j0, N - 1)], jb = bid[jend];
    if (ib < ja || ia > jb) return;
  }

  int t = threadIdx.x;
  {
    // t in [0,64): r = t>>2, c = t&3 covers all TI*4 slots
    int r = t >> 2, c = t & 3;
    int gic = min(i0 + r, N - 1);
    const float* p = X + (size_t)gic * 12 + c * 3;
    float x = p[0], y = p[1], z = p[2];
    sNX[r][c][0] = pk2(-2.0f * x, -2.0f * x);
    sNX[r][c][1] = pk2(-2.0f * y, -2.0f * y);
    sNX[r][c][2] = pk2(-2.0f * z, -2.0f * z);
    float sic = x * x + y * y + z * z;
    sSicp[r][c] = pk2(sic, sic);
    if (c == 0) { sB[r] = bid[gic]; sS[r] = Seg[gic]; }
  }

  int jA = j0 + 2 * t, jB = jA + 1;
  int jAc = min(jA, N - 1), jBc = min(jB, N - 1);
  const float4* pa = (const float4*)(X + (size_t)jAc * 12);
  const float4* pb = (const float4*)(X + (size_t)jBc * 12);
  float4 a0 = pa[0], a1 = pa[1], a2 = pa[2];
  float4 b0 = pb[0], b1 = pb[1], b2 = pb[2];
  float xa[12] = {a0.x, a0.y, a0.z, a0.w, a1.x, a1.y,
                  a1.z, a1.w, a2.x, a2.y, a2.z, a2.w};
  float xb[12] = {b0.x, b0.y, b0.z, b0.w, b1.x, b1.y,
                  b1.z, b1.w, b2.x, b2.y, b2.z, b2.w};
  unsigned long long xjp[4][3], sqjp[4];
#pragma unroll
  for (int e = 0; e < 4; e++) {
#pragma unroll
    for (int d = 0; d < 3; d++) xjp[e][d] = pk2(xa[e * 3 + d], xb[e * 3 + d]);
    sqjp[e] = fma2_(xjp[e][0], xjp[e][0],
                    fma2_(xjp[e][1], xjp[e][1], mul2_(xjp[e][2], xjp[e][2])));
  }
  int bidA = bid[jAc], segA = Seg[jAc];
  int bidB = bid[jBc], segB = Seg[jBc];
  sBj[2 * t] = bidA;
  sBj[2 * t + 1] = bidB;
  __syncthreads();

  for (int r = 0; r < TI; r++) {
    int i = i0 + r;
    if (i >= N) break;
    if (jB < i) continue;
    int bi_ = sB[r], si_ = sS[r];
    if (bi_ != bidA && bi_ != bidB) continue;  // cross-group: never read
    float best0 = 3.4e38f, best1 = 3.4e38f;
#pragma unroll
    for (int c = 0; c < 4; c++) {
      unsigned long long nx0 = sNX[r][c][0];
      unsigned long long nx1 = sNX[r][c][1];
      unsigned long long nx2 = sNX[r][c][2];
      unsigned long long sic = sSicp[r][c];
#pragma unroll
      for (int e = 0; e < 4; e++) {
        unsigned long long seed = add2_(sic, sqjp[e]);
        unsigned long long d2 =
            fma2_(nx0, xjp[e][0],
                  fma2_(nx1, xjp[e][1], fma2_(nx2, xjp[e][2], seed)));
        float d20, d21;
        upk2(d2, d20, d21);
        best0 = fminf(best0, d20);
        best1 = fminf(best1, d21);
      }
    }
    float d0 = (bi_ == bidA && si_ == segA) ? sqrtf(fmaxf(best0, 0.0f)) : BIGF;
    float d1 = (bi_ == bidB && si_ == segB) ? sqrtf(fmaxf(best1, 0.0f)) : BIGF;
    size_t base = (size_t)i * N + jA;
    if (jA >= i && jB < N && (base & 1) == 0) {
      *(unsigned long long*)(g_dist + base) = pk2(d0, d1);
    } else {
      if (jA >= i && jA < N) g_dist[base] = d0;
      if (jB >= i && jB < N) g_dist[base + 1] = d1;
    }
    sD[r][2 * t] = d0;
    sD[r][2 * t + 1] = d1;
  }
  __syncthreads();

  // Mirror: only same-bid (actually-computed, possibly-read) entries.
  for (int idx = t; idx < TI * TJ; idx += DTHREADS) {
    int jr = idx >> 4;
    int rr = idx & 15;
    int j = j0 + jr, i = i0 + rr;
    if (j < N && i < N && j > i && sBj[jr] == sB[rr])
      g_dist[(size_t)j * N + i] = sD[rr][jr];
  }
}

// ---------------------------------------------------------------------------
// Dihedral helpers
// ---------------------------------------------------------------------------
__device__ __forceinline__ float3 ldatom(const float* __restrict__ X, int n, int c) {
  const float* p = X + (size_t)n * 12 + c * 3;
  return make_float3(p[0], p[1], p[2]);
}
__device__ __forceinline__ float3 f3sub(float3 a, float3 b) {
  return make_float3(a.x - b.x, a.y - b.y, a.z - b.z);
}
__device__ __forceinline__ float3 f3cross(float3 a, float3 b) {
  return make_float3(a.y * b.z - a.z * b.y, a.z * b.x - a.x * b.z,
                     a.x * b.y - a.y * b.x);
}
__device__ __forceinline__ float f3dot(float3 a, float3 b) {
  return a.x * b.x + a.y * b.y + a.z * b.z;
}
__device__ __forceinline__ float dihedral4(float3 a, float3 b, float3 c, float3 d) {
  float3 u1 = f3sub(b, a), u2 = f3sub(c, b), u3 = f3sub(d, c);
  float3 n1 = f3cross(u1, u2), n2 = f3cross(u2, u3);
  float nrm = sqrtf(f3dot(u2, u2)) + 1e-12f;
  float3 u2n = make_float3(u2.x / nrm, u2.y / nrm, u2.z / nrm);
  float3 m = f3cross(n1, u2n);
  return atan2f(f3dot(m, n2), f3dot(n1, n2));
}

// Insert v into sorted-ascending (vals, idxs); strict < keeps earlier index
// first on ties (ascending-j scan per lane) — jax.lax.top_k semantics.
__device__ __forceinline__ void tk_ins_f(float* vals, int* idxs, float v, int j) {
  const int K = 10;
  vals[K - 1] = v;
  idxs[K - 1] = j;
#pragma unroll
  for (int m = K - 1; m > 0; m--) {
    if (vals[m] < vals[m - 1]) {
      float tv = vals[m]; vals[m] = vals[m - 1]; vals[m - 1] = tv;
      int ti = idxs[m]; idxs[m] = idxs[m - 1]; idxs[m - 1] = ti;
    }
  }
}

// Warp merge of 32 sorted 10-lists in shw; shw[0..9] = warp top-10 after.
__device__ __forceinline__ void warp_merge10(unsigned long long* shw, int lane) {
  const int K = 10;
  for (int h = 16; h >= 1; h >>= 1) {
    if (lane < h) {
      unsigned long long mg[K];
      int p = 0, q = 0;
#pragma unroll
      for (int m = 0; m < K; m++) {
        unsigned long long av = shw[lane * K + p];
        unsigned long long bv = shw[(lane + h) * K + q];
        if (av <= bv) { mg[m] = av; p++; }
        else          { mg[m] = bv; q++; }
      }
#pragma unroll
      for (int m = 0; m < K; m++) shw[lane * K + m] = mg[m];
    }
    __syncwarp();
  }
}

// ---------------------------------------------------------------------------
// Fused kernel (R12/R14 structure): node features + restricted top-10 over
// g_dist + dihedrals. ONE WARP PER ROW. Epilogue dihedrals spread over 20
// lanes (lane<10: phi + edges/valid; lanes 10-19: psi).
// ---------------------------------------------------------------------------
__global__ __launch_bounds__(128) void fused_topk_kernel(
    const float* __restrict__ X, const int* __restrict__ bid,
    const float* __restrict__ res_embed, const float* __restrict__ id_embed,
    const int* __restrict__ S, const int* __restrict__ RP,
    const int* __restrict__ ID, int N, int E, float* __restrict__ out,
    size_t offE, size_t offA, size_t offV) {
  const int K = 10;
  const float INF = __int_as_float(0x7f800000);
  int t = threadIdx.x;
  int w = t >> 5, lane = t & 31;
  int i = blockIdx.x * 4 + w;   // one row per warp
  if (i >= N) return;

  __shared__ unsigned long long sh[4][32 * K];
  unsigned long long* shw = sh[w];

  // ---- node features for row i ----
  float* orow = out + (size_t)i * (2 * E);
  for (int tt = lane; tt < E; tt += 32) orow[tt] = res_embed[S[i] * E + tt];
  for (int p = lane; p < E / 2; p += 32) {
    float freq = exp2f((float)p * (-2.0f * 13.287712379549449f / (float)E));
    float ang = (float)RP[i] * freq;
    float s, c;
    sincosf(ang, &s, &c);
    const float* id = id_embed + ID[i] * E;
    orow[E + 2 * p] = s + id[2 * p];
    orow[E + 2 * p + 1] = c + id[2 * p + 1];
  }

  // ---- group bounds via binary search on sorted bid (+ safety clamp) ----
  int myb = bid[i];
  int lo, hi;
  {
    int a = 0, b = N;
    while (a < b) { int m = (a + b) >> 1; if (bid[m] < myb) a = m + 1; else b = m; }
    lo = a;
  }
  {
    int a = lo, b = N;
    while (a < b) { int m = (a + b) >> 1; if (bid[m] <= myb) a = m + 1; else b = m; }
    hi = a;
  }
  lo = min(lo, i);
  hi = max(hi, i + 1);

  // ---- restricted scan of g_dist row i over [lo, hi) ----
  const float* row = g_dist + (size_t)i * N;
  float vals[K];
  int idxs[K];
#pragma unroll
  for (int m = 0; m < K; m++) { vals[m] = INF; idxs[m] = 0x7fffffff; }

  int lo4 = (lo + 3) & ~3;
  if (lo4 > hi) lo4 = hi;
  int hi4 = lo4 + ((hi - lo4) & ~3);

  for (int j = lo + lane; j < lo4; j += 32) {
    float v = row[j];
    if (v < vals[K - 1]) tk_ins_f(vals, idxs, v, j);
  }
  for (int j = lo4 + lane * 4; j < hi4; j += 128) {
    float4 v = *(const float4*)(row + j);
    float mn = fminf(fminf(v.x, v.y), fminf(v.z, v.w));
    if (mn < vals[K - 1]) {
      if (v.x < vals[K - 1]) tk_ins_f(vals, idxs, v.x, j + 0);
      if (v.y < vals[K - 1]) tk_ins_f(vals, idxs, v.y, j + 1);
      if (v.z < vals[K - 1]) tk_ins_f(vals, idxs, v.z, j + 2);
      if (v.w < vals[K - 1]) tk_ins_f(vals, idxs, v.w, j + 3);
    }
  }
  for (int j = hi4 + lane; j < hi; j += 32) {
    float v = row[j];
    if (v < vals[K - 1]) tk_ins_f(vals, idxs, v, j);
  }

  // ---- warp merge over 32 sorted 10-lists (u64 (val<<32)|j keys) ----
#pragma unroll
  for (int m = 0; m < K; m++)
    shw[lane * K + m] =
        ((unsigned long long)__float_as_uint(vals[m]) << 32) |
        (unsigned int)idxs[m];
  __syncwarp();
  warp_merge10(shw, lane);

  // ---- epilogue: lanes 0..19 each compute ONE dihedral; lanes 0..9 also
  //      write edges/valid ----
  if (lane < 2 * K) {
    int slot = (lane < K) ? lane : lane - K;
    unsigned long long key = shw[slot];
    unsigned int j = (unsigned int)key;
    float v = __uint_as_float((unsigned int)(key >> 32));
    bool valid = (v < BIGF);
    int e = i * K + slot;

    int dj = valid ? (int)j : 0;
    int si = valid ? i : 0;

    if (lane < K) {
      out[offE + e] = valid ? (float)j : -1.0f;                 // edges[0]
      out[offE + (size_t)N * K + e] = valid ? (float)i : -1.0f; // edges[1]
      out[offV + e] = valid ? 1.0f : 0.0f;
      // ir_phi = dihedral(C_i, N_j, CA_j, C_j)
      float3 dC = ldatom(X, dj, 2);
      float3 sN = ldatom(X, si, 0), sCA = ldatom(X, si, 1), sC = ldatom(X, si, 2);
      float phi = dihedral4(dC, sN, sCA, sC);
      out[offA + 2 * (size_t)e + 0] = valid ? phi : 0.0f;
    } else {
      // ir_psi = dihedral(N_i, CA_i, C_i, N_j)
      float3 dN = ldatom(X, dj, 0), dCA = ldatom(X, dj, 1), dC = ldatom(X, dj, 2);
      float3 sN = ldatom(X, si, 0);
      float psi = dihedral4(dN, dCA, dC, sN);
      out[offA + 2 * (size_t)e + 1] = valid ? psi : 0.0f;
    }
  }
}

// ---------------------------------------------------------------------------
// Fallback path for k != 10 (full-matrix; BIGF pre-fill makes skips safe)
// ---------------------------------------------------------------------------
__global__ void fill_big_kernel(int N) {
  size_t idx = (size_t)blockIdx.x * blockDim.x + threadIdx.x;
  size_t total = (size_t)N * N;
  for (; idx < total; idx += (size_t)gridDim.x * blockDim.x) g_dist[idx] = BIGF;
}

__global__ void node_feat_kernel(const float* __restrict__ res_embed,
                                 const float* __restrict__ id_embed,
                                 const int* __restrict__ S,
                                 const int* __restrict__ RP,
                                 const int* __restrict__ ID,
                                 float* __restrict__ out, int N, int E) {
  int i = blockIdx.x;
  int t = threadIdx.x;
  if (i >= N) return;
  float* orow = out + (size_t)i * (2 * E);
  for (int tt = t; tt < E; tt += blockDim.x) orow[tt] = res_embed[S[i] * E + tt];
  for (int p = t; p < E / 2; p += blockDim.x) {
    float freq = exp2f((float)p * (-2.0f * 13.287712379549449f / (float)E));
    float ang = (float)RP[i] * freq;
    float s, c;
    sincosf(ang, &s, &c);
    const float* id = id_embed + ID[i] * E;
    orow[E + 2 * p] = s + id[2 * p];
    orow[E + 2 * p + 1] = c + id[2 * p + 1];
  }
}

__global__ void topk_generic_kernel(int N, int k, float* __restrict__ out,
                                    size_t offE, size_t offV) {
  int i = blockIdx.x * blockDim.x + threadIdx.x;
  if (i >= N) return;
  unsigned long long loc[KMAXG];
  for (int m = 0; m < k; m++) loc[m] = ~0ull;
  const float* row = g_dist + (size_t)i * N;
  for (int j = 0; j < N; j++) {
    unsigned long long key =
        ((unsigned long long)__float_as_uint(row[j]) << 32) | (unsigned int)j;
    if (key < loc[k - 1]) {
      loc[k - 1] = key;
      for (int m = k - 1; m > 0; m--) {
        if (loc[m] < loc[m - 1]) {
          unsigned long long tmp = loc[m];
          loc[m] = loc[m - 1];
          loc[m - 1] = tmp;
        }
      }
    }
  }
  for (int m = 0; m < k; m++) {
    unsigned long long key = loc[m];
    unsigned int j = (unsigned int)key;
    float v = __uint_as_float((unsigned int)(key >> 32));
    bool valid = (v < BIGF);
    int e = i * k + m;
    out[offE + e] = valid ? (float)j : -1.0f;
    out[offE + (size_t)N * k + e] = valid ? (float)i : -1.0f;
    out[offV + e] = valid ? 1.0f : 0.0f;
    g_dst[e] = valid ? (int)j : 0;
    g_src[e] = valid ? i : 0;
    g_val[e] = valid ? 1 : 0;
  }
}

__global__ void edge_attr_kernel(const float* __restrict__ X,
                                 float* __restrict__ out, size_t offA, int NE) {
  int e = blockIdx.x * blockDim.x + threadIdx.x;
  if (e >= NE) return;
  int dj = g_dst[e], si = g_src[e];
  float3 dN = ldatom(X, dj, 0), dCA = ldatom(X, dj, 1), dC = ldatom(X, dj, 2);
  float3 sN = ldatom(X, si, 0), sCA = ldatom(X, si, 1), sC = ldatom(X, si, 2);
  float phi = dihedral4(dC, sN, sCA, sC);
  float psi = dihedral4(dN, dCA, dC, sN);
  bool v = (g_val[e] != 0);
  out[offA + 2 * (size_t)e + 0] = v ? phi : 0.0f;
  out[offA + 2 * (size_t)e + 1] = v ? psi : 0.0f;
}

// ---------------------------------------------------------------------------
// Launcher. Output = concat(H[N,2E], edges[2,N*k], edge_attr[N*k,2], valid[N*k])
// ---------------------------------------------------------------------------
extern "C" void kernel_launch(void* const* d_in, const int* in_sizes, int n_in,
                              void* d_out, int out_size) {
  const float* X = (const float*)d_in[0];
  const int* S = (const int*)d_in[1];
  const int* RP = (const int*)d_in[2];
  const int* ID = (const int*)d_in[3];
  const int* Seg = (const int*)d_in[4];
  const int* bid = (const int*)d_in[5];
  const float* res_embed = (const float*)d_in[6];
  const float* id_embed = (const float*)d_in[7];
  float* out = (float*)d_out;

  int N = in_sizes[0] / 12;
  int E = in_sizes[7] / 2;
  long long rem = (long long)out_size - 2LL * E * N;
  int k = (int)(rem / (5LL * N));
  if (k < 1) k = 1;
  if (k > KMAXG) k = KMAXG;

  size_t offE = (size_t)N * 2 * E;
  size_t offA = offE + (size_t)2 * N * k;
  size_t offV = offA + (size_t)2 * N * k;

  dim3 dgrid((N + TJ - 1) / TJ, (N + TI - 1) / TI);

  if (k == 10) {
    dist_kernel<<<dgrid, DTHREADS>>>(X, Seg, bid, N);
    fused_topk_kernel<<<(N + 3) / 4, 128>>>(X, bid, res_embed, id_embed, S, RP,
                                            ID, N, E, out, offE, offA, offV);
  } else {
    fill_big_kernel<<<1024, 256>>>(N);
    dist_kernel<<<dgrid, DTHREADS>>>(X, Seg, bid, N);
    node_feat_kernel<<<N, 128>>>(res_embed, id_embed, S, RP, ID, out, N, E);
    topk_generic_kernel<<<(N + 63) / 64, 64>>>(N, k, out, offE, offV);
    edge_attr_kernel<<<(N * k + 127) / 128, 128>>>(X, out, offA, N * k);
  }
}

// round 16
// speedup vs baseline: 1.4486x; 1.4486x over previous
#include <cuda_runtime.h>
#include <math.h>
#include <stdint.h>

#define BIGF 1e10f
#define NMAX 3072
#define KMAXG 64
#define TI 16
#define TJ 128
#define TJP 129
#define DTHREADS 64

// Scratch (fallback path only; no allocations allowed).
__device__ float g_dist[(size_t)NMAX * NMAX];
__device__ int g_dst[NMAX * KMAXG];
__device__ int g_src[NMAX * KMAXG];
__device__ unsigned char g_val[NMAX * KMAXG];

// ---------------------------------------------------------------------------
// Packed f32x2 helpers (fallback dist kernel)
// ---------------------------------------------------------------------------
static __device__ __forceinline__ unsigned long long pk2(float a, float b) {
  unsigned long long r;
  asm("mov.b64 %0, {%1,%2};" : "=l"(r) : "f"(a), "f"(b));
  return r;
}
static __device__ __forceinline__ void upk2(unsigned long long v, float& a, float& b) {
  asm("mov.b64 {%0,%1}, %2;" : "=f"(a), "=f"(b) : "l"(v));
}
static __device__ __forceinline__ unsigned long long fma2_(unsigned long long a,
                                                           unsigned long long b,
                                                           unsigned long long c) {
  unsigned long long r;
  asm("fma.rn.f32x2 %0, %1, %2, %3;" : "=l"(r) : "l"(a), "l"(b), "l"(c));
  return r;
}
static __device__ __forceinline__ unsigned long long mul2_(unsigned long long a,
                                                           unsigned long long b) {
  unsigned long long r;
  asm("mul.rn.f32x2 %0, %1, %2;" : "=l"(r) : "l"(a), "l"(b));
  return r;
}
static __device__ __forceinline__ unsigned long long add2_(unsigned long long a,
                                                           unsigned long long b) {
  unsigned long long r;
  asm("add.rn.f32x2 %0, %1, %2;" : "=l"(r) : "l"(a), "l"(b));
  return r;
}

// ---------------------------------------------------------------------------
// Dihedral helpers
// ---------------------------------------------------------------------------
__device__ __forceinline__ float3 ldatom(const float* __restrict__ X, int n, int c) {
  const float* p = X + (size_t)n * 12 + c * 3;
  return make_float3(p[0], p[1], p[2]);
}
__device__ __forceinline__ float3 f3sub(float3 a, float3 b) {
  return make_float3(a.x - b.x, a.y - b.y, a.z - b.z);
}
__device__ __forceinline__ float3 f3cross(float3 a, float3 b) {
  return make_float3(a.y * b.z - a.z * b.y, a.z * b.x - a.x * b.z,
                     a.x * b.y - a.y * b.x);
}
__device__ __forceinline__ float f3dot(float3 a, float3 b) {
  return a.x * b.x + a.y * b.y + a.z * b.z;
}
__device__ __forceinline__ float dihedral4(float3 a, float3 b, float3 c, float3 d) {
  float3 u1 = f3sub(b, a), u2 = f3sub(c, b), u3 = f3sub(d, c);
  float3 n1 = f3cross(u1, u2), n2 = f3cross(u2, u3);
  float nrm = sqrtf(f3dot(u2, u2)) + 1e-12f;
  float3 u2n = make_float3(u2.x / nrm, u2.y / nrm, u2.z / nrm);
  float3 m = f3cross(n1, u2n);
  return atan2f(f3dot(m, n2), f3dot(n1, n2));
}

// Insert v into sorted-ascending (vals, idxs); strict < keeps earlier index
// first on ties (ascending-j scan per lane) — jax.lax.top_k semantics.
__device__ __forceinline__ void tk_ins_f(float* vals, int* idxs, float v, int j) {
  const int K = 10;
  vals[K - 1] = v;
  idxs[K - 1] = j;
#pragma unroll
  for (int m = K - 1; m > 0; m--) {
    if (vals[m] < vals[m - 1]) {
      float tv = vals[m]; vals[m] = vals[m - 1]; vals[m - 1] = tv;
      int ti = idxs[m]; idxs[m] = idxs[m - 1]; idxs[m - 1] = ti;
    }
  }
}

// Warp merge of 32 sorted 10-lists in shw; shw[0..9] = warp top-10 after.
__device__ __forceinline__ void warp_merge10(unsigned long long* shw, int lane) {
  const int K = 10;
  for (int h = 16; h >= 1; h >>= 1) {
    if (lane < h) {
      unsigned long long mg[K];
      int p = 0, q = 0;
#pragma unroll
      for (int m = 0; m < K; m++) {
        unsigned long long av = shw[lane * K + p];
        unsigned long long bv = shw[(lane + h) * K + q];
        if (av <= bv) { mg[m] = av; p++; }
        else          { mg[m] = bv; q++; }
      }
#pragma unroll
      for (int m = 0; m < K; m++) shw[lane * K + m] = mg[m];
    }
    __syncwarp();
  }
}

// ---------------------------------------------------------------------------
// SINGLE FUSED KERNEL (k==10): node features + group-local knn + dihedrals.
// Distances replicate the proven two-kernel pipeline's values BITWISE:
//   sqA(p)[c] = x*x + y*y + z*z            (same source expr as dist's sic)
//   sqB(p)[c] = fmaf(x,x, fmaf(y,y, z*z))  (packed-chain structure)
//   seed(a,b) = (j>=i) ? sqA_i[a]+sqB_j[b] : sqB_i[a]+sqA_j[b]
//   d2 = fmaf(nxi[a][0],xj[b][0], fmaf(nxi[a][1],xj[b][1],
//             fmaf(nxi[a][2],xj[b][2], seed)))           (nx = -2*x exact)
//   d  = (Seg match) ? sqrtf(fmaxf(min d2, 0)) : BIGF
// The j<i case reproduces the mirror's swapped-role arithmetic because the
// FMA products are exact under operand swap and FADD/min are commutative.
// ---------------------------------------------------------------------------
__global__ __launch_bounds__(128) void knn_all_kernel(
    const float* __restrict__ X, const int* __restrict__ Seg,
    const int* __restrict__ bid, const float* __restrict__ res_embed,
    const float* __restrict__ id_embed, const int* __restrict__ S,
    const int* __restrict__ RP, const int* __restrict__ ID, int N, int E,
    float* __restrict__ out, size_t offE, size_t offA, size_t offV) {
  const int K = 10;
  const float INF = __int_as_float(0x7f800000);
  int t = threadIdx.x;
  int w = t >> 5, lane = t & 31;
  int i = blockIdx.x * 4 + w;   // one row per warp
  if (i >= N) return;

  __shared__ unsigned long long sh[4][32 * K];
  unsigned long long* shw = sh[w];

  // ---- node features for row i ----
  float* orow = out + (size_t)i * (2 * E);
  for (int tt = lane; tt < E; tt += 32) orow[tt] = res_embed[S[i] * E + tt];
  for (int p = lane; p < E / 2; p += 32) {
    float freq = exp2f((float)p * (-2.0f * 13.287712379549449f / (float)E));
    float ang = (float)RP[i] * freq;
    float s, c;
    sincosf(ang, &s, &c);
    const float* id = id_embed + ID[i] * E;
    orow[E + 2 * p] = s + id[2 * p];
    orow[E + 2 * p + 1] = c + id[2 * p + 1];
  }

  // ---- group bounds via binary search on sorted bid (+ safety clamp) ----
  int myb = bid[i];
  int lo, hi;
  {
    int a = 0, b = N;
    while (a < b) { int m = (a + b) >> 1; if (bid[m] < myb) a = m + 1; else b = m; }
    lo = a;
  }
  {
    int a = lo, b = N;
    while (a < b) { int m = (a + b) >> 1; if (bid[m] <= myb) a = m + 1; else b = m; }
    hi = a;
  }
  lo = min(lo, i);
  hi = max(hi, i + 1);
  int myseg = Seg[i];

  // ---- X[i]: coords, -2x (exact), and both norm structures ----
  const float4* xi4 = (const float4*)(X + (size_t)i * 12);
  float4 q0 = xi4[0], q1 = xi4[1], q2 = xi4[2];
  float xi[12] = {q0.x, q0.y, q0.z, q0.w, q1.x, q1.y,
                  q1.z, q1.w, q2.x, q2.y, q2.z, q2.w};
  float nxi[12], sqAi[4], sqBi[4];
#pragma unroll
  for (int c = 0; c < 4; c++) {
    float x = xi[c * 3], y = xi[c * 3 + 1], z = xi[c * 3 + 2];
    sqAi[c] = x * x + y * y + z * z;                 // dist's sic expression
    sqBi[c] = fmaf(x, x, fmaf(y, y, z * z));         // packed-chain structure
    nxi[c * 3] = -2.0f * x;
    nxi[c * 3 + 1] = -2.0f * y;
    nxi[c * 3 + 2] = -2.0f * z;
  }

  // ---- group scan: lane covers j = lo+lane, +32, ... (ascending) ----
  float vals[K];
  int idxs[K];
#pragma unroll
  for (int m = 0; m < K; m++) { vals[m] = INF; idxs[m] = 0x7fffffff; }

  for (int j = lo + lane; j < hi; j += 32) {
    const float4* xj4 = (const float4*)(X + (size_t)j * 12);
    float4 a0 = xj4[0], a1 = xj4[1], a2 = xj4[2];
    int segj = Seg[j];
    float xj[12] = {a0.x, a0.y, a0.z, a0.w, a1.x, a1.y,
                    a1.z, a1.w, a2.x, a2.y, a2.z, a2.w};
    bool jge = (j >= i);
    float sqj[4];
#pragma unroll
    for (int b = 0; b < 4; b++) {
      float x = xj[b * 3], y = xj[b * 3 + 1], z = xj[b * 3 + 2];
      if (jge) sqj[b] = fmaf(x, x, fmaf(y, y, z * z));   // sqB(j)
      else     sqj[b] = x * x + y * y + z * z;           // sqA(j)
    }
    float best = 3.4e38f;
#pragma unroll
    for (int a = 0; a < 4; a++) {
      float sqi_sel = jge ? sqAi[a] : sqBi[a];
#pragma unroll
      for (int b = 0; b < 4; b++) {
        float seed = sqi_sel + sqj[b];
        float d2 = fmaf(nxi[a * 3], xj[b * 3],
                        fmaf(nxi[a * 3 + 1], xj[b * 3 + 1],
                             fmaf(nxi[a * 3 + 2], xj[b * 3 + 2], seed)));
        best = fminf(best, d2);
      }
    }
    float d = (segj == myseg) ? sqrtf(fmaxf(best, 0.0f)) : BIGF;
    if (d < vals[K - 1]) tk_ins_f(vals, idxs, d, j);
  }

  // ---- warp merge over 32 sorted 10-lists (u64 (val<<32)|j keys) ----
#pragma unroll
  for (int m = 0; m < K; m++)
    shw[lane * K + m] =
        ((unsigned long long)__float_as_uint(vals[m]) << 32) |
        (unsigned int)idxs[m];
  __syncwarp();
  warp_merge10(shw, lane);

  // ---- epilogue: edges, valid, dihedrals (lanes 0..9) ----
  if (lane < K) {
    unsigned long long key = shw[lane];
    unsigned int j = (unsigned int)key;
    float v = __uint_as_float((unsigned int)(key >> 32));
    bool valid = (v < BIGF);
    int e = i * K + lane;
    out[offE + e] = valid ? (float)j : -1.0f;                 // edges[0] (dst)
    out[offE + (size_t)N * K + e] = valid ? (float)i : -1.0f; // edges[1] (src)
    out[offV + e] = valid ? 1.0f : 0.0f;

    int dj = valid ? (int)j : 0;
    int si = valid ? i : 0;
    float3 dN = ldatom(X, dj, 0), dCA = ldatom(X, dj, 1), dC = ldatom(X, dj, 2);
    float3 sN = ldatom(X, si, 0), sCA = ldatom(X, si, 1), sC = ldatom(X, si, 2);
    float phi = dihedral4(dC, sN, sCA, sC);   // C_i, N_j, CA_j, C_j
    float psi = dihedral4(dN, dCA, dC, sN);   // N_i, CA_i, C_i, N_j
    out[offA + 2 * (size_t)e + 0] = valid ? phi : 0.0f;
    out[offA + 2 * (size_t)e + 1] = valid ? psi : 0.0f;
  }
}

// ---------------------------------------------------------------------------
// Fallback path (k != 10): proven full-matrix pipeline.
// ---------------------------------------------------------------------------
__global__ __launch_bounds__(DTHREADS) void dist_kernel(
    const float* __restrict__ X, const int* __restrict__ Seg,
    const int* __restrict__ bid, int N) {
  __shared__ unsigned long long sNX[TI][4][3];
  __shared__ unsigned long long sSicp[TI][4];
  __shared__ int sB[TI], sS[TI];
  __shared__ int sBj[TJ];
  __shared__ float sD[TI][TJP];

  int i0 = blockIdx.y * TI;
  int j0 = blockIdx.x * TJ;
  if (j0 + TJ - 1 < i0) return;
  {
    int iend = min(i0 + TI - 1, N - 1);
    int jend = min(j0 + TJ - 1, N - 1);
    int ia = bid[min(i0, N - 1)], ib = bid[iend];
    int ja = bid[min(j0, N - 1)], jb = bid[jend];
    if (ib < ja || ia > jb) return;
  }

  int t = threadIdx.x;
  {
    int r = t >> 2, c = t & 3;
    int gic = min(i0 + r, N - 1);
    const float* p = X + (size_t)gic * 12 + c * 3;
    float x = p[0], y = p[1], z = p[2];
    sNX[r][c][0] = pk2(-2.0f * x, -2.0f * x);
    sNX[r][c][1] = pk2(-2.0f * y, -2.0f * y);
    sNX[r][c][2] = pk2(-2.0f * z, -2.0f * z);
    float sic = x * x + y * y + z * z;
    sSicp[r][c] = pk2(sic, sic);
    if (c == 0) { sB[r] = bid[gic]; sS[r] = Seg[gic]; }
  }

  int jA = j0 + 2 * t, jB = jA + 1;
  int jAc = min(jA, N - 1), jBc = min(jB, N - 1);
  const float4* pa = (const float4*)(X + (size_t)jAc * 12);
  const float4* pb = (const float4*)(X + (size_t)jBc * 12);
  float4 a0 = pa[0], a1 = pa[1], a2 = pa[2];
  float4 b0 = pb[0], b1 = pb[1], b2 = pb[2];
  float xa[12] = {a0.x, a0.y, a0.z, a0.w, a1.x, a1.y,
                  a1.z, a1.w, a2.x, a2.y, a2.z, a2.w};
  float xb[12] = {b0.x, b0.y, b0.z, b0.w, b1.x, b1.y,
                  b1.z, b1.w, b2.x, b2.y, b2.z, b2.w};
  unsigned long long xjp[4][3], sqjp[4];
#pragma unroll
  for (int e = 0; e < 4; e++) {
#pragma unroll
    for (int d = 0; d < 3; d++) xjp[e][d] = pk2(xa[e * 3 + d], xb[e * 3 + d]);
    sqjp[e] = fma2_(xjp[e][0], xjp[e][0],
                    fma2_(xjp[e][1], xjp[e][1], mul2_(xjp[e][2], xjp[e][2])));
  }
  int bidA = bid[jAc], segA = Seg[jAc];
  int bidB = bid[jBc], segB = Seg[jBc];
  sBj[2 * t] = bidA;
  sBj[2 * t + 1] = bidB;
  __syncthreads();

  for (int r = 0; r < TI; r++) {
    int i = i0 + r;
    if (i >= N) break;
    if (jB < i) continue;
    int bi_ = sB[r], si_ = sS[r];
    if (bi_ != bidA && bi_ != bidB) continue;
    float best0 = 3.4e38f, best1 = 3.4e38f;
#pragma unroll
    for (int c = 0; c < 4; c++) {
      unsigned long long nx0 = sNX[r][c][0];
      unsigned long long nx1 = sNX[r][c][1];
      unsigned long long nx2 = sNX[r][c][2];
      unsigned long long sic = sSicp[r][c];
#pragma unroll
      for (int e = 0; e < 4; e++) {
        unsigned long long seed = add2_(sic, sqjp[e]);
        unsigned long long d2 =
            fma2_(nx0, xjp[e][0],
                  fma2_(nx1, xjp[e][1], fma2_(nx2, xjp[e][2], seed)));
        float d20, d21;
        upk2(d2, d20, d21);
        best0 = fminf(best0, d20);
        best1 = fminf(best1, d21);
      }
    }
    float d0 = (bi_ == bidA && si_ == segA) ? sqrtf(fmaxf(best0, 0.0f)) : BIGF;
    float d1 = (bi_ == bidB && si_ == segB) ? sqrtf(fmaxf(best1, 0.0f)) : BIGF;
    size_t base = (size_t)i * N + jA;
    if (jA >= i && jB < N && (base & 1) == 0) {
      *(unsigned long long*)(g_dist + base) = pk2(d0, d1);
    } else {
      if (jA >= i && jA < N) g_dist[base] = d0;
      if (jB >= i && jB < N) g_dist[base + 1] = d1;
    }
    sD[r][2 * t] = d0;
    sD[r][2 * t + 1] = d1;
  }
  __syncthreads();

  for (int idx = t; idx < TI * TJ; idx += DTHREADS) {
    int jr = idx >> 4;
    int rr = idx & 15;
    int j = j0 + jr, i = i0 + rr;
    if (j < N && i < N && j > i && sBj[jr] == sB[rr])
      g_dist[(size_t)j * N + i] = sD[rr][jr];
  }
}

__global__ void fill_big_kernel(int N) {
  size_t idx = (size_t)blockIdx.x * blockDim.x + threadIdx.x;
  size_t total = (size_t)N * N;
  for (; idx < total; idx += (size_t)gridDim.x * blockDim.x) g_dist[idx] = BIGF;
}

__global__ void node_feat_kernel(const float* __restrict__ res_embed,
                                 const float* __restrict__ id_embed,
                                 const int* __restrict__ S,
                                 const int* __restrict__ RP,
                                 const int* __restrict__ ID,
                                 float* __restrict__ out, int N, int E) {
  int i = blockIdx.x;
  int t = threadIdx.x;
  if (i >= N) return;
  float* orow = out + (size_t)i * (2 * E);
  for (int tt = t; tt < E; tt += blockDim.x) orow[tt] = res_embed[S[i] * E + tt];
  for (int p = t; p < E / 2; p += blockDim.x) {
    float freq = exp2f((float)p * (-2.0f * 13.287712379549449f / (float)E));
    float ang = (float)RP[i] * freq;
    float s, c;
    sincosf(ang, &s, &c);
    const float* id = id_embed + ID[i] * E;
    orow[E + 2 * p] = s + id[2 * p];
    orow[E + 2 * p + 1] = c + id[2 * p + 1];
  }
}

__global__ void topk_generic_kernel(int N, int k, float* __restrict__ out,
                                    size_t offE, size_t offV) {
  int i = blockIdx.x * blockDim.x + threadIdx.x;
  if (i >= N) return;
  unsigned long long loc[KMAXG];
  for (int m = 0; m < k; m++) loc[m] = ~0ull;
  const float* row = g_dist + (size_t)i * N;
  for (int j = 0; j < N; j++) {
    unsigned long long key =
        ((unsigned long long)__float_as_uint(row[j]) << 32) | (unsigned int)j;
    if (key < loc[k - 1]) {
      loc[k - 1] = key;
      for (int m = k - 1; m > 0; m--) {
        if (loc[m] < loc[m - 1]) {
          unsigned long long tmp = loc[m];
          loc[m] = loc[m - 1];
          loc[m - 1] = tmp;
        }
      }
    }
  }
  for (int m = 0; m < k; m++) {
    unsigned long long key = loc[m];
    unsigned int j = (unsigned int)key;
    float v = __uint_as_float((unsigned int)(key >> 32));
    bool valid = (v < BIGF);
    int e = i * k + m;
    out[offE + e] = valid ? (float)j : -1.0f;
    out[offE + (size_t)N * k + e] = valid ? (float)i : -1.0f;
    out[offV + e] = valid ? 1.0f : 0.0f;
    g_dst[e] = valid ? (int)j : 0;
    g_src[e] = valid ? i : 0;
    g_val[e] = valid ? 1 : 0;
  }
}

__global__ void edge_attr_kernel(const float* __restrict__ X,
                                 float* __restrict__ out, size_t offA, int NE) {
  int e = blockIdx.x * blockDim.x + threadIdx.x;
  if (e >= NE) return;
  int dj = g_dst[e], si = g_src[e];
  float3 dN = ldatom(X, dj, 0), dCA = ldatom(X, dj, 1), dC = ldatom(X, dj, 2);
  float3 sN = ldatom(X, si, 0), sCA = ldatom(X, si, 1), sC = ldatom(X, si, 2);
  float phi = dihedral4(dC, sN, sCA, sC);
  float psi = dihedral4(dN, dCA, dC, sN);
  bool v = (g_val[e] != 0);
  out[offA + 2 * (size_t)e + 0] = v ? phi : 0.0f;
  out[offA + 2 * (size_t)e + 1] = v ? psi : 0.0f;
}

// ---------------------------------------------------------------------------
// Launcher. Output = concat(H[N,2E], edges[2,N*k], edge_attr[N*k,2], valid[N*k])
// ---------------------------------------------------------------------------
extern "C" void kernel_launch(void* const* d_in, const int* in_sizes, int n_in,
                              void* d_out, int out_size) {
  const float* X = (const float*)d_in[0];
  const int* S = (const int*)d_in[1];
  const int* RP = (const int*)d_in[2];
  const int* ID = (const int*)d_in[3];
  const int* Seg = (const int*)d_in[4];
  const int* bid = (const int*)d_in[5];
  const float* res_embed = (const float*)d_in[6];
  const float* id_embed = (const float*)d_in[7];
  float* out = (float*)d_out;

  int N = in_sizes[0] / 12;
  int E = in_sizes[7] / 2;
  long long rem = (long long)out_size - 2LL * E * N;
  int k = (int)(rem / (5LL * N));
  if (k < 1) k = 1;
  if (k > KMAXG) k = KMAXG;

  size_t offE = (size_t)N * 2 * E;
  size_t offA = offE + (size_t)2 * N * k;
  size_t offV = offA + (size_t)2 * N * k;

  if (k == 10) {
    knn_all_kernel<<<(N + 3) / 4, 128>>>(X, Seg, bid, res_embed, id_embed, S,
                                         RP, ID, N, E, out, offE, offA, offV);
  } else {
    dim3 dgrid((N + TJ - 1) / TJ, (N + TI - 1) / TI);
    fill_big_kernel<<<1024, 256>>>(N);
    dist_kernel<<<dgrid, DTHREADS>>>(X, Seg, bid, N);
    node_feat_kernel<<<N, 128>>>(res_embed, id_embed, S, RP, ID, out, N, E);
    topk_generic_kernel<<<(N + 63) / 64, 64>>>(N, k, out, offE, offV);
    edge_attr_kernel<<<(N * k + 127) / 128, 128>>>(X, out, offA, N * k);
  }
}